// round 14
// baseline (speedup 1.0000x reference)
#include <cuda_runtime.h>
#include <cstdint>

#define BB 8
#define NN 8192
#define SS 1024
#define KK 32
static constexpr int M_ROWS = BB * SS * KK;   // 262144
static constexpr float EPSf = 1e-5f;

typedef unsigned long long ull;

// ---------------- packed f32x2 helpers (rn — bit-identical to scalar) -------
__device__ __forceinline__ ull pack2(float lo, float hi) {
    ull v; asm("mov.b64 %0, {%1, %2};" : "=l"(v) : "f"(lo), "f"(hi)); return v;
}
__device__ __forceinline__ void unpack2(ull v, float& lo, float& hi) {
    asm("mov.b64 {%0, %1}, %2;" : "=f"(lo), "=f"(hi) : "l"(v));
}
__device__ __forceinline__ ull add2(ull a, ull b) {
    ull d; asm("add.rn.f32x2 %0, %1, %2;" : "=l"(d) : "l"(a), "l"(b)); return d;
}
__device__ __forceinline__ ull mul2(ull a, ull b) {
    ull d; asm("mul.rn.f32x2 %0, %1, %2;" : "=l"(d) : "l"(a), "l"(b)); return d;
}
__device__ __forceinline__ ull fma2(ull a, ull b, ull c) {
    ull d; asm("fma.rn.f32x2 %0, %1, %2, %3;" : "=l"(d) : "l"(a), "l"(b), "l"(c)); return d;
}

// ------------------------------ device scratch ------------------------------
__device__ float  g_h0[(size_t)M_ROWS * 64];     // layer0 pre-BN   64 MB
__device__ float  g_h1[(size_t)M_ROWS * 64];     // layer1 pre-BN   64 MB
__device__ float  g_mx[(size_t)BB * SS * 128];   // per-query raw max (layer2)
__device__ float  g_mn[(size_t)BB * SS * 128];   // per-query raw min (layer2)
__device__ int    g_gidx[M_ROWS];
__device__ double g_sum[256];
__device__ double g_sq[256];
__device__ float  g_a[256];
__device__ float  g_cs[256];

__global__ void k_init() {
    int i = threadIdx.x;
    if (i < 256) { g_sum[i] = 0.0; g_sq[i] = 0.0; }
}

// -------------------------- FPS: one CTA per batch ---------------------------
// 512 threads x 16 points. f32x2 distance math (exact rn semantics). Running
// distances kept as UINT BIT PATTERNS (dist >= 0 -> float order == uint order),
// so min-update and the argmax tree use IMNMX.U32 on the ALU pipe, leaving the
// fma pipe at its 448-cyc f32x2 floor. Tie-breaks via ballot+ffs (min lane ==
// min tid == min point index). Selection bit-identical to prior rounds.
__global__ void __launch_bounds__(512, 1)
k_fps(const float* __restrict__ xyz, float* __restrict__ out) {
    int b = blockIdx.x;
    const float* X = xyz + (size_t)b * NN * 3;
    int tid = threadIdx.x;
    int base = tid * 16;                         // 16 points per thread

    // load 16 points = 48 floats = 12 float4
    float f[48];
    const float4* Xv = (const float4*)(X + (size_t)base * 3);
#pragma unroll
    for (int i = 0; i < 12; i++) {
        float4 v = Xv[i];
        f[i * 4 + 0] = v.x; f[i * 4 + 1] = v.y; f[i * 4 + 2] = v.z; f[i * 4 + 3] = v.w;
    }
    ull cxp[8], cyp[8], czp[8];
#pragma unroll
    for (int g = 0; g < 8; g++) {
        cxp[g] = pack2(f[(2 * g) * 3 + 0], f[(2 * g + 1) * 3 + 0]);
        cyp[g] = pack2(f[(2 * g) * 3 + 1], f[(2 * g + 1) * 3 + 1]);
        czp[g] = pack2(f[(2 * g) * 3 + 2], f[(2 * g + 1) * 3 + 2]);
    }
    unsigned du[16];                              // dist bits (uint order == float order)
#pragma unroll
    for (int j = 0; j < 16; j++) du[j] = __float_as_uint(1e10f);

    __shared__ __align__(16) ull s_cp[4];    // negated packed centroid
    __shared__ ull s_key[32];                // warp keys (16 valid; 16..31 neutral 0)
    int lane = tid & 31;
    int warp = tid >> 5;                     // 0..15

    if (tid >= 16 && tid < 32) s_key[tid] = 0ull;
    if (tid == 0) {
        s_cp[0] = pack2(-f[0], -f[0]);
        s_cp[1] = pack2(-f[1], -f[1]);
        s_cp[2] = pack2(-f[2], -f[2]);
        float* o = out + (size_t)b * SS * 3;
        o[0] = f[0]; o[1] = f[1]; o[2] = f[2];
    }
    __syncthreads();

    for (int s = 1; s < SS; s++) {
        ulonglong2 cp01 = *reinterpret_cast<const ulonglong2*>(&s_cp[0]);  // LDS.128
        ull cp2 = s_cp[2];                                                 // LDS.64

#pragma unroll
        for (int g = 0; g < 8; g++) {
            ull dx = add2(cxp[g], cp01.x);
            ull dy = add2(cyp[g], cp01.y);
            ull dz = add2(czp[g], cp2);
            ull d  = add2(add2(mul2(dx, dx), mul2(dy, dy)), mul2(dz, dz));
            float da, db; unpack2(d, da, db);
            du[2 * g]     = umin(du[2 * g],     __float_as_uint(da));   // IMNMX (alu)
            du[2 * g + 1] = umin(du[2 * g + 1], __float_as_uint(db));
        }

        // value-only max tree over 16 (uint, alu pipe)
        unsigned t8[8];
#pragma unroll
        for (int g = 0; g < 8; g++) t8[g] = umax(du[2 * g], du[2 * g + 1]);
        unsigned t40 = umax(t8[0], t8[1]), t41 = umax(t8[2], t8[3]);
        unsigned t42 = umax(t8[4], t8[5]), t43 = umax(t8[6], t8[7]);
        unsigned bb  = umax(umax(t40, t41), umax(t42, t43));

        // stage 1: warp max value; min-tid tiebreak via ballot+ffs
        unsigned m    = __reduce_max_sync(0xffffffffu, bb);
        unsigned msk  = __ballot_sync(0xffffffffu, bb == m);
        int      l1   = __ffs(msk) - 1;                 // lowest lane == lowest tid
        if (lane == l1) s_key[warp] = ((ull)m << 32) | (unsigned)tid;
        __syncthreads();

        // stage 2: all warps redundantly reduce over 16 warp keys (+16 neutral)
        ull k = s_key[lane];
        unsigned wb = (unsigned)(k >> 32);
        unsigned m2   = __reduce_max_sync(0xffffffffu, wb);
        unsigned msk2 = __ballot_sync(0xffffffffu, wb == m2);
        int      w2   = __ffs(msk2) - 1;                // lowest warp == lowest tid range
        unsigned t2   = __shfl_sync(0xffffffffu, (unsigned)k, w2);

        if ((unsigned)tid == t2) {
            // first j (ascending) with dist bits == m2
            int j = 0;
#pragma unroll
            for (int jj = 15; jj >= 0; jj--)
                if (du[jj] == m2) j = jj;
            int g = j >> 1;
            ull vx = cxp[0], vy = cyp[0], vz = czp[0];
#pragma unroll
            for (int gg = 1; gg < 8; gg++) {
                vx = (g == gg) ? cxp[gg] : vx;
                vy = (g == gg) ? cyp[gg] : vy;
                vz = (g == gg) ? czp[gg] : vz;
            }
            float xl, xh, yl, yh, zl, zh;
            unpack2(vx, xl, xh); unpack2(vy, yl, yh); unpack2(vz, zl, zh);
            float X0 = (j & 1) ? xh : xl;
            float Y0 = (j & 1) ? yh : yl;
            float Z0 = (j & 1) ? zh : zl;
            s_cp[0] = pack2(-X0, -X0);
            s_cp[1] = pack2(-Y0, -Y0);
            s_cp[2] = pack2(-Z0, -Z0);
            float* o = out + ((size_t)b * SS + s) * 3;
            o[0] = X0; o[1] = Y0; o[2] = Z0;
        }
        __syncthreads();
    }
}

// ------------------------ Ball query: one warp per query ---------------------
__global__ void __launch_bounds__(256)
k_ball(const float* __restrict__ xyz, const float* __restrict__ newxyz) {
    const float R2 = (float)(0.2 * 0.2);
    int warp = threadIdx.x >> 5, lane = threadIdx.x & 31;
    int q = blockIdx.x * 8 + warp;
    int b = q >> 10;
    const float* X = xyz + (size_t)b * NN * 3;
    float nx = newxyz[q * 3], ny = newxyz[q * 3 + 1], nz = newxyz[q * 3 + 2];
    float s2 = __fadd_rn(__fadd_rn(__fmul_rn(nx, nx), __fmul_rn(ny, ny)),
                         __fmul_rn(nz, nz));
    __shared__ int s_list[8][KK];
    int found = 0;
    for (int basep = 0; basep < NN; basep += 32) {
        int n = basep + lane;
        float x = X[n * 3], y = X[n * 3 + 1], z = X[n * 3 + 2];
        float n2  = __fadd_rn(__fadd_rn(__fmul_rn(x, x), __fmul_rn(y, y)),
                              __fmul_rn(z, z));
        float dot = __fadd_rn(__fadd_rn(__fmul_rn(nx, x), __fmul_rn(ny, y)),
                              __fmul_rn(nz, z));
        float sq  = __fsub_rn(__fadd_rn(s2, n2), __fmul_rn(2.0f, dot));
        bool pass = !(sq > R2);
        unsigned msk = __ballot_sync(0xffffffffu, pass);
        int pos = found + __popc(msk & ((1u << lane) - 1u));
        if (pass && pos < KK) s_list[warp][pos] = n;
        found += __popc(msk);
        if (found >= KK) break;
    }
    __syncwarp();
    int cnt = found < KK ? found : KK;
    int first = s_list[warp][0];
    int v = (lane < cnt) ? s_list[warp][lane] : first;
    g_gidx[q * KK + lane] = v;
}

// ---------------- Layer0: gather + 9->64 matmul (f32x2) + stats --------------
__global__ void __launch_bounds__(256)
k_layer0(const float* __restrict__ points, const float* __restrict__ xyz,
         const float* __restrict__ newxyz, const float* __restrict__ W0,
         const float* __restrict__ b0) {
    __shared__ __align__(16) float s_W[9 * 64];
    __shared__ __align__(16) float s_b[64];
    __shared__ __align__(16) int   s_idx[128];
    __shared__ __align__(16) ull   s_f2[2][16][9];
    __shared__ float s_red[16][64];
    int tid = threadIdx.x;
    int row0 = blockIdx.x * 128;
    for (int i = tid; i < 576; i += 256) s_W[i] = W0[i];
    if (tid < 64) s_b[tid] = b0[tid];
    if (tid < 32) *reinterpret_cast<int4*>(&s_idx[tid * 4]) =
        *reinterpret_cast<const int4*>(&g_gidx[row0 + tid * 4]);
    __syncthreads();

    int r = tid >> 4, cg = tid & 15, c0 = cg * 4;
    ulonglong2 bp = *reinterpret_cast<const ulonglong2*>(&s_b[c0]);
    ull ls01 = 0, ls23 = 0, lq01 = 0, lq23 = 0;

    const bool ld = tid < 144;
    int lrr = tid / 9, lj = tid - lrr * 9;
    const int bidx = row0 >> 15;

    auto load_feat = [&](int t) -> float {
        int row = row0 + t * 16 + lrr;
        int i = s_idx[t * 16 + lrr];
        if (lj < 6) {
            return points[((size_t)bidx * NN + i) * 6 + lj];
        } else {
            int q = row >> 5, cc = lj - 6;
            return xyz[((size_t)bidx * NN + i) * 3 + cc] - newxyz[(size_t)q * 3 + cc];
        }
    };

    float fcur = 0.f;
    if (ld) fcur = load_feat(0);

    for (int t = 0; t < 8; t++) {
        if (ld) s_f2[t & 1][lrr][lj] = pack2(fcur, fcur);
        __syncthreads();
        if (ld && t < 7) fcur = load_feat(t + 1);

        ull a01 = bp.x, a23 = bp.y;
#pragma unroll
        for (int j = 0; j < 9; j++) {
            ull f = s_f2[t & 1][r][j];
            ulonglong2 w = *reinterpret_cast<const ulonglong2*>(&s_W[j * 64 + c0]);
            a01 = fma2(f, w.x, a01);
            a23 = fma2(f, w.y, a23);
        }
        ulonglong2 o; o.x = a01; o.y = a23;
        *reinterpret_cast<ulonglong2*>(&g_h0[(size_t)(row0 + t * 16 + r) * 64 + c0]) = o;
        ls01 = add2(ls01, a01); ls23 = add2(ls23, a23);
        lq01 = fma2(a01, a01, lq01); lq23 = fma2(a23, a23, lq23);
    }
    float l0, l1, l2, l3;
    unpack2(ls01, l0, l1); unpack2(ls23, l2, l3);
    s_red[r][c0] = l0; s_red[r][c0+1] = l1; s_red[r][c0+2] = l2; s_red[r][c0+3] = l3;
    __syncthreads();
    if (tid < 64) {
        float t0 = 0.f;
#pragma unroll
        for (int rr = 0; rr < 16; rr++) t0 += s_red[rr][tid];
        atomicAdd(&g_sum[tid], (double)t0);
    }
    __syncthreads();
    unpack2(lq01, l0, l1); unpack2(lq23, l2, l3);
    s_red[r][c0] = l0; s_red[r][c0+1] = l1; s_red[r][c0+2] = l2; s_red[r][c0+3] = l3;
    __syncthreads();
    if (tid < 64) {
        float t0 = 0.f;
#pragma unroll
        for (int rr = 0; rr < 16; rr++) t0 += s_red[rr][tid];
        atomicAdd(&g_sq[tid], (double)t0);
    }
}

// -------------------------------- BN finalize --------------------------------
__global__ void k_finalize(const float* __restrict__ g, const float* __restrict__ be,
                           int off, int C) {
    int c = threadIdx.x;
    if (c < C) {
        const double invM = 1.0 / (double)M_ROWS;
        double m = g_sum[off + c] * invM;
        double v = g_sq[off + c] * invM - m * m;
        float rs = rsqrtf((float)v + EPSf);
        float a = g[c] * rs;
        g_a[off + c] = a;
        g_cs[off + c] = fmaf(-(float)m, a, be[c]);
    }
}

// -------------- Layer1: bn0+relu, 64->64 matmul (f32x2), stats ---------------
__global__ void __launch_bounds__(256)
k_layer1(const float* __restrict__ W1, const float* __restrict__ b1) {
    __shared__ __align__(16) float s_W[64 * 64];
    __shared__ __align__(16) float s_b[64];
    __shared__ float s_a[64], s_cs[64];
    __shared__ __align__(16) ull s_x2[32][64];
    __shared__ float s_red[16][64];
    int tid = threadIdx.x;
    for (int i = tid; i < 4096; i += 256) s_W[i] = W1[i];
    if (tid < 64) { s_b[tid] = b1[tid]; s_a[tid] = g_a[tid]; s_cs[tid] = g_cs[tid]; }
    __syncthreads();
    int rg = tid >> 4, cg = tid & 15, c0 = cg * 4;
    int r0 = rg * 2;
    ulonglong2 bp = *reinterpret_cast<const ulonglong2*>(&s_b[c0]);
    ull ls01 = 0, ls23 = 0, lq01 = 0, lq23 = 0;

    for (int t = 0; t < 4; t++) {
        int row0 = (blockIdx.x * 4 + t) * 32;
#pragma unroll
        for (int e = 0; e < 4; e++) {
            int lin = e * 256 + tid;
            int rr = lin >> 5, jj = (lin & 31) * 2;
            float2 v = *reinterpret_cast<const float2*>(&g_h0[(size_t)(row0 + rr) * 64 + jj]);
            float v0 = fmaxf(fmaf(v.x, s_a[jj],     s_cs[jj]),     0.f);
            float v1 = fmaxf(fmaf(v.y, s_a[jj + 1], s_cs[jj + 1]), 0.f);
            ulonglong2 st; st.x = pack2(v0, v0); st.y = pack2(v1, v1);
            *reinterpret_cast<ulonglong2*>(&s_x2[rr][jj]) = st;
        }
        __syncthreads();
        ull a01_0 = bp.x, a23_0 = bp.y, a01_1 = bp.x, a23_1 = bp.y;
#pragma unroll
        for (int j = 0; j < 64; j++) {
            ull x0 = s_x2[r0][j], x1 = s_x2[r0 + 1][j];
            ulonglong2 w = *reinterpret_cast<const ulonglong2*>(&s_W[j * 64 + c0]);
            a01_0 = fma2(x0, w.x, a01_0); a23_0 = fma2(x0, w.y, a23_0);
            a01_1 = fma2(x1, w.x, a01_1); a23_1 = fma2(x1, w.y, a23_1);
        }
        ulonglong2 o;
        o.x = a01_0; o.y = a23_0;
        *reinterpret_cast<ulonglong2*>(&g_h1[(size_t)(row0 + r0) * 64 + c0]) = o;
        o.x = a01_1; o.y = a23_1;
        *reinterpret_cast<ulonglong2*>(&g_h1[(size_t)(row0 + r0 + 1) * 64 + c0]) = o;
        ls01 = add2(add2(ls01, a01_0), a01_1);
        ls23 = add2(add2(ls23, a23_0), a23_1);
        lq01 = fma2(a01_0, a01_0, lq01); lq01 = fma2(a01_1, a01_1, lq01);
        lq23 = fma2(a23_0, a23_0, lq23); lq23 = fma2(a23_1, a23_1, lq23);
        __syncthreads();
    }
    float l0, l1, l2, l3;
    unpack2(ls01, l0, l1); unpack2(ls23, l2, l3);
    s_red[rg][c0] = l0; s_red[rg][c0+1] = l1; s_red[rg][c0+2] = l2; s_red[rg][c0+3] = l3;
    __syncthreads();
    if (tid < 64) {
        float t0 = 0.f;
#pragma unroll
        for (int rr = 0; rr < 16; rr++) t0 += s_red[rr][tid];
        atomicAdd(&g_sum[64 + tid], (double)t0);
    }
    __syncthreads();
    unpack2(lq01, l0, l1); unpack2(lq23, l2, l3);
    s_red[rg][c0] = l0; s_red[rg][c0+1] = l1; s_red[rg][c0+2] = l2; s_red[rg][c0+3] = l3;
    __syncthreads();
    if (tid < 64) {
        float t0 = 0.f;
#pragma unroll
        for (int rr = 0; rr < 16; rr++) t0 += s_red[rr][tid];
        atomicAdd(&g_sq[64 + tid], (double)t0);
    }
}

// ------ Layer2: bn1+relu, 64->128 matmul (f32x2), stats, fused max/min ------
__global__ void __launch_bounds__(256)
k_layer2(const float* __restrict__ W2, const float* __restrict__ b2) {
    __shared__ __align__(16) float s_W[64 * 128];
    __shared__ __align__(16) float s_b[128];
    __shared__ float s_a[64], s_cs[64];
    __shared__ __align__(16) ull s_x2[16][64];
    __shared__ float s_red[8][128];
    int tid = threadIdx.x;
    for (int i = tid; i < 8192; i += 256) s_W[i] = W2[i];
    if (tid < 128) s_b[tid] = b2[tid];
    if (tid < 64) { s_a[tid] = g_a[64 + tid]; s_cs[tid] = g_cs[64 + tid]; }
    __syncthreads();
    int rg = tid >> 5, cg = tid & 31, c0 = cg * 4;
    int r0 = rg * 2;
    ulonglong2 bp = *reinterpret_cast<const ulonglong2*>(&s_b[c0]);
    ull ls01 = 0, ls23 = 0, lq01 = 0, lq23 = 0;
    float mx0 = -3.402823466e38f, mx1 = mx0, mx2 = mx0, mx3 = mx0;
    float mn0 =  3.402823466e38f, mn1 = mn0, mn2 = mn0, mn3 = mn0;

    for (int t = 0; t < 8; t++) {
        int row0 = (blockIdx.x * 8 + t) * 16;
#pragma unroll
        for (int e = 0; e < 2; e++) {
            int lin = e * 256 + tid;
            int rr = lin >> 5, jj = (lin & 31) * 2;
            float2 v = *reinterpret_cast<const float2*>(&g_h1[(size_t)(row0 + rr) * 64 + jj]);
            float v0 = fmaxf(fmaf(v.x, s_a[jj],     s_cs[jj]),     0.f);
            float v1 = fmaxf(fmaf(v.y, s_a[jj + 1], s_cs[jj + 1]), 0.f);
            ulonglong2 st; st.x = pack2(v0, v0); st.y = pack2(v1, v1);
            *reinterpret_cast<ulonglong2*>(&s_x2[rr][jj]) = st;
        }
        __syncthreads();
        ull a01_0 = bp.x, a23_0 = bp.y, a01_1 = bp.x, a23_1 = bp.y;
#pragma unroll
        for (int j = 0; j < 64; j++) {
            ull x0 = s_x2[r0][j], x1 = s_x2[r0 + 1][j];
            ulonglong2 w = *reinterpret_cast<const ulonglong2*>(&s_W[j * 128 + c0]);
            a01_0 = fma2(x0, w.x, a01_0); a23_0 = fma2(x0, w.y, a23_0);
            a01_1 = fma2(x1, w.x, a01_1); a23_1 = fma2(x1, w.y, a23_1);
        }
        ls01 = add2(add2(ls01, a01_0), a01_1);
        ls23 = add2(add2(ls23, a23_0), a23_1);
        lq01 = fma2(a01_0, a01_0, lq01); lq01 = fma2(a01_1, a01_1, lq01);
        lq23 = fma2(a23_0, a23_0, lq23); lq23 = fma2(a23_1, a23_1, lq23);

        float e0, e1, e2, e3, f0, f1, f2, f3;
        unpack2(a01_0, e0, e1); unpack2(a23_0, e2, e3);
        unpack2(a01_1, f0, f1); unpack2(a23_1, f2, f3);
        mx0 = fmaxf(mx0, fmaxf(e0, f0)); mn0 = fminf(mn0, fminf(e0, f0));
        mx1 = fmaxf(mx1, fmaxf(e1, f1)); mn1 = fminf(mn1, fminf(e1, f1));
        mx2 = fmaxf(mx2, fmaxf(e2, f2)); mn2 = fminf(mn2, fminf(e2, f2));
        mx3 = fmaxf(mx3, fmaxf(e3, f3)); mn3 = fminf(mn3, fminf(e3, f3));

        if (t & 1) {
            int q = blockIdx.x * 4 + (t >> 1);
            s_red[rg][c0] = mx0; s_red[rg][c0+1] = mx1; s_red[rg][c0+2] = mx2; s_red[rg][c0+3] = mx3;
            __syncthreads();
            if (tid < 128) {
                float m = s_red[0][tid];
#pragma unroll
                for (int rr = 1; rr < 8; rr++) m = fmaxf(m, s_red[rr][tid]);
                g_mx[(size_t)q * 128 + tid] = m;
            }
            __syncthreads();
            s_red[rg][c0] = mn0; s_red[rg][c0+1] = mn1; s_red[rg][c0+2] = mn2; s_red[rg][c0+3] = mn3;
            __syncthreads();
            if (tid < 128) {
                float m = s_red[0][tid];
#pragma unroll
                for (int rr = 1; rr < 8; rr++) m = fminf(m, s_red[rr][tid]);
                g_mn[(size_t)q * 128 + tid] = m;
            }
            mx0 = mx1 = mx2 = mx3 = -3.402823466e38f;
            mn0 = mn1 = mn2 = mn3 =  3.402823466e38f;
        }
        __syncthreads();
    }
    float l0, l1, l2, l3;
    unpack2(ls01, l0, l1); unpack2(ls23, l2, l3);
    s_red[rg][c0] = l0; s_red[rg][c0+1] = l1; s_red[rg][c0+2] = l2; s_red[rg][c0+3] = l3;
    __syncthreads();
    if (tid < 128) {
        float t0 = 0.f;
#pragma unroll
        for (int rr = 0; rr < 8; rr++) t0 += s_red[rr][tid];
        atomicAdd(&g_sum[128 + tid], (double)t0);
    }
    __syncthreads();
    unpack2(lq01, l0, l1); unpack2(lq23, l2, l3);
    s_red[rg][c0] = l0; s_red[rg][c0+1] = l1; s_red[rg][c0+2] = l2; s_red[rg][c0+3] = l3;
    __syncthreads();
    if (tid < 128) {
        float t0 = 0.f;
#pragma unroll
        for (int rr = 0; rr < 8; rr++) t0 += s_red[rr][tid];
        atomicAdd(&g_sq[128 + tid], (double)t0);
    }
}

// --------- Final: BN2+relu applied to per-query max/min (exact fusion) -------
__global__ void __launch_bounds__(256)
k_out(float* __restrict__ out) {
    int i = blockIdx.x * 256 + threadIdx.x;
    int c = i & 127;
    float a = g_a[128 + c], cs = g_cs[128 + c];
    float v = (a >= 0.f) ? g_mx[i] : g_mn[i];
    out[(size_t)BB * SS * 3 + i] = fmaxf(fmaf(v, a, cs), 0.f);
}

// -----------------------------------------------------------------------------
extern "C" void kernel_launch(void* const* d_in, const int* in_sizes, int n_in,
                              void* d_out, int out_size) {
    const float* xyz    = (const float*)d_in[0];
    const float* points = (const float*)d_in[1];
    const float* W0 = (const float*)d_in[2];  const float* b0 = (const float*)d_in[3];
    const float* g0 = (const float*)d_in[4];  const float* be0 = (const float*)d_in[5];
    const float* W1 = (const float*)d_in[6];  const float* b1 = (const float*)d_in[7];
    const float* g1 = (const float*)d_in[8];  const float* be1 = (const float*)d_in[9];
    const float* W2 = (const float*)d_in[10]; const float* b2 = (const float*)d_in[11];
    const float* g2 = (const float*)d_in[12]; const float* be2 = (const float*)d_in[13];
    float* out = (float*)d_out;   // [B*S*3 new_xyz | B*S*128 new_points]

    k_init<<<1, 256>>>();
    k_fps<<<BB, 512>>>(xyz, out);
    k_ball<<<(BB * SS) / 8, 256>>>(xyz, out);
    k_layer0<<<2048, 256>>>(points, xyz, out, W0, b0);
    k_finalize<<<1, 64>>>(g0, be0, 0, 64);
    k_layer1<<<2048, 256>>>(W1, b1);
    k_finalize<<<1, 64>>>(g1, be1, 64, 64);
    k_layer2<<<2048, 256>>>(W2, b2);
    k_finalize<<<1, 128>>>(g2, be2, 128, 128);
    k_out<<<(BB * SS * 128) / 256, 256>>>(out);
}

// round 15
// speedup vs baseline: 1.1019x; 1.1019x over previous
#include <cuda_runtime.h>
#include <cstdint>

#define BB 8
#define NN 8192
#define SS 1024
#define KK 32
static constexpr int M_ROWS = BB * SS * KK;   // 262144
static constexpr float EPSf = 1e-5f;

typedef unsigned long long ull;

// ---------------- packed f32x2 helpers (rn — bit-identical to scalar) -------
__device__ __forceinline__ ull pack2(float lo, float hi) {
    ull v; asm("mov.b64 %0, {%1, %2};" : "=l"(v) : "f"(lo), "f"(hi)); return v;
}
__device__ __forceinline__ void unpack2(ull v, float& lo, float& hi) {
    asm("mov.b64 {%0, %1}, %2;" : "=f"(lo), "=f"(hi) : "l"(v));
}
__device__ __forceinline__ ull add2(ull a, ull b) {
    ull d; asm("add.rn.f32x2 %0, %1, %2;" : "=l"(d) : "l"(a), "l"(b)); return d;
}
__device__ __forceinline__ ull mul2(ull a, ull b) {
    ull d; asm("mul.rn.f32x2 %0, %1, %2;" : "=l"(d) : "l"(a), "l"(b)); return d;
}
__device__ __forceinline__ ull fma2(ull a, ull b, ull c) {
    ull d; asm("fma.rn.f32x2 %0, %1, %2, %3;" : "=l"(d) : "l"(a), "l"(b), "l"(c)); return d;
}

// ------------------------------ device scratch ------------------------------
__device__ float  g_h0[(size_t)M_ROWS * 64];     // layer0 pre-BN   64 MB
__device__ float  g_h1[(size_t)M_ROWS * 64];     // layer1 pre-BN   64 MB
__device__ float  g_mx[(size_t)BB * SS * 128];   // per-query raw max (layer2)
__device__ float  g_mn[(size_t)BB * SS * 128];   // per-query raw min (layer2)
__device__ int    g_gidx[M_ROWS];
__device__ double g_sum[256];
__device__ double g_sq[256];
__device__ float  g_a[256];
__device__ float  g_cs[256];

__global__ void k_init() {
    int i = threadIdx.x;
    if (i < 256) { g_sum[i] = 0.0; g_sq[i] = 0.0; }
}

// -------------------------- FPS: one CTA per batch ---------------------------
// (R13 version — best measured.) 512 threads x 16 points, f32x2 rn math,
// FMNMX value tree, two-stage (value, tid) REDUX, winner broadcasts centroid.
__global__ void __launch_bounds__(512, 1)
k_fps(const float* __restrict__ xyz, float* __restrict__ out) {
    int b = blockIdx.x;
    const float* X = xyz + (size_t)b * NN * 3;
    int tid = threadIdx.x;
    int base = tid * 16;

    float f[48];
    const float4* Xv = (const float4*)(X + (size_t)base * 3);
#pragma unroll
    for (int i = 0; i < 12; i++) {
        float4 v = Xv[i];
        f[i * 4 + 0] = v.x; f[i * 4 + 1] = v.y; f[i * 4 + 2] = v.z; f[i * 4 + 3] = v.w;
    }
    ull cxp[8], cyp[8], czp[8];
#pragma unroll
    for (int g = 0; g < 8; g++) {
        cxp[g] = pack2(f[(2 * g) * 3 + 0], f[(2 * g + 1) * 3 + 0]);
        cyp[g] = pack2(f[(2 * g) * 3 + 1], f[(2 * g + 1) * 3 + 1]);
        czp[g] = pack2(f[(2 * g) * 3 + 2], f[(2 * g + 1) * 3 + 2]);
    }
    float dist[16];
#pragma unroll
    for (int j = 0; j < 16; j++) dist[j] = 1e10f;

    __shared__ __align__(16) ull s_cp[4];
    __shared__ ull s_key[32];
    int lane = tid & 31;
    int warp = tid >> 5;

    if (tid >= 16 && tid < 32) s_key[tid] = 0ull;
    if (tid == 0) {
        s_cp[0] = pack2(-f[0], -f[0]);
        s_cp[1] = pack2(-f[1], -f[1]);
        s_cp[2] = pack2(-f[2], -f[2]);
        float* o = out + (size_t)b * SS * 3;
        o[0] = f[0]; o[1] = f[1]; o[2] = f[2];
    }
    __syncthreads();

    for (int s = 1; s < SS; s++) {
        ulonglong2 cp01 = *reinterpret_cast<const ulonglong2*>(&s_cp[0]);
        ull cp2 = s_cp[2];

#pragma unroll
        for (int g = 0; g < 8; g++) {
            ull dx = add2(cxp[g], cp01.x);
            ull dy = add2(cyp[g], cp01.y);
            ull dz = add2(czp[g], cp2);
            ull d  = add2(add2(mul2(dx, dx), mul2(dy, dy)), mul2(dz, dz));
            float da, db; unpack2(d, da, db);
            dist[2 * g]     = fminf(dist[2 * g],     da);
            dist[2 * g + 1] = fminf(dist[2 * g + 1], db);
        }

        float t8[8];
#pragma unroll
        for (int g = 0; g < 8; g++) t8[g] = fmaxf(dist[2 * g], dist[2 * g + 1]);
        float t40 = fmaxf(t8[0], t8[1]), t41 = fmaxf(t8[2], t8[3]);
        float t42 = fmaxf(t8[4], t8[5]), t43 = fmaxf(t8[6], t8[7]);
        float best = fmaxf(fmaxf(t40, t41), fmaxf(t42, t43));

        unsigned bb   = __float_as_uint(best);
        unsigned m    = __reduce_max_sync(0xffffffffu, bb);
        unsigned cand = (bb == m) ? (unsigned)tid : 0xffffffffu;
        unsigned mi   = __reduce_min_sync(0xffffffffu, cand);
        if (lane == 0) s_key[warp] = ((ull)m << 32) | (ull)mi;
        __syncthreads();

        ull k = s_key[lane];
        unsigned wb = (unsigned)(k >> 32);
        unsigned m2 = __reduce_max_sync(0xffffffffu, wb);
        unsigned c2 = (wb == m2) ? (unsigned)k : 0xffffffffu;
        unsigned t2 = __reduce_min_sync(0xffffffffu, c2);

        if ((unsigned)tid == t2) {
            int j = 0;
#pragma unroll
            for (int jj = 15; jj >= 0; jj--)
                if (__float_as_uint(dist[jj]) == m2) j = jj;
            int g = j >> 1;
            ull vx = cxp[0], vy = cyp[0], vz = czp[0];
#pragma unroll
            for (int gg = 1; gg < 8; gg++) {
                vx = (g == gg) ? cxp[gg] : vx;
                vy = (g == gg) ? cyp[gg] : vy;
                vz = (g == gg) ? czp[gg] : vz;
            }
            float xl, xh, yl, yh, zl, zh;
            unpack2(vx, xl, xh); unpack2(vy, yl, yh); unpack2(vz, zl, zh);
            float X0 = (j & 1) ? xh : xl;
            float Y0 = (j & 1) ? yh : yl;
            float Z0 = (j & 1) ? zh : zl;
            s_cp[0] = pack2(-X0, -X0);
            s_cp[1] = pack2(-Y0, -Y0);
            s_cp[2] = pack2(-Z0, -Z0);
            float* o = out + ((size_t)b * SS + s) * 3;
            o[0] = X0; o[1] = Y0; o[2] = Z0;
        }
        __syncthreads();
    }
}

// ------------------------ Ball query: one warp per query ---------------------
__global__ void __launch_bounds__(256)
k_ball(const float* __restrict__ xyz, const float* __restrict__ newxyz) {
    const float R2 = (float)(0.2 * 0.2);
    int warp = threadIdx.x >> 5, lane = threadIdx.x & 31;
    int q = blockIdx.x * 8 + warp;
    int b = q >> 10;
    const float* X = xyz + (size_t)b * NN * 3;
    float nx = newxyz[q * 3], ny = newxyz[q * 3 + 1], nz = newxyz[q * 3 + 2];
    float s2 = __fadd_rn(__fadd_rn(__fmul_rn(nx, nx), __fmul_rn(ny, ny)),
                         __fmul_rn(nz, nz));
    __shared__ int s_list[8][KK];
    int found = 0;
    for (int basep = 0; basep < NN; basep += 32) {
        int n = basep + lane;
        float x = X[n * 3], y = X[n * 3 + 1], z = X[n * 3 + 2];
        float n2  = __fadd_rn(__fadd_rn(__fmul_rn(x, x), __fmul_rn(y, y)),
                              __fmul_rn(z, z));
        float dot = __fadd_rn(__fadd_rn(__fmul_rn(nx, x), __fmul_rn(ny, y)),
                              __fmul_rn(nz, z));
        float sq  = __fsub_rn(__fadd_rn(s2, n2), __fmul_rn(2.0f, dot));
        bool pass = !(sq > R2);
        unsigned msk = __ballot_sync(0xffffffffu, pass);
        int pos = found + __popc(msk & ((1u << lane) - 1u));
        if (pass && pos < KK) s_list[warp][pos] = n;
        found += __popc(msk);
        if (found >= KK) break;
    }
    __syncwarp();
    int cnt = found < KK ? found : KK;
    int first = s_list[warp][0];
    int v = (lane < cnt) ? s_list[warp][lane] : first;
    g_gidx[q * KK + lane] = v;
}

// ---------------- Layer0: gather + 9->64 matmul (f32x2) + stats --------------
__global__ void __launch_bounds__(256)
k_layer0(const float* __restrict__ points, const float* __restrict__ xyz,
         const float* __restrict__ newxyz, const float* __restrict__ W0,
         const float* __restrict__ b0) {
    __shared__ __align__(16) float s_W[9 * 64];
    __shared__ __align__(16) float s_b[64];
    __shared__ __align__(16) int   s_idx[128];
    __shared__ __align__(16) ull   s_f2[2][16][9];
    __shared__ float s_red[16][64];
    int tid = threadIdx.x;
    int row0 = blockIdx.x * 128;
    for (int i = tid; i < 576; i += 256) s_W[i] = W0[i];
    if (tid < 64) s_b[tid] = b0[tid];
    if (tid < 32) *reinterpret_cast<int4*>(&s_idx[tid * 4]) =
        *reinterpret_cast<const int4*>(&g_gidx[row0 + tid * 4]);
    __syncthreads();

    int r = tid >> 4, cg = tid & 15, c0 = cg * 4;
    ulonglong2 bp = *reinterpret_cast<const ulonglong2*>(&s_b[c0]);
    ull ls01 = 0, ls23 = 0, lq01 = 0, lq23 = 0;

    const bool ld = tid < 144;
    int lrr = tid / 9, lj = tid - lrr * 9;
    const int bidx = row0 >> 15;

    auto load_feat = [&](int t) -> float {
        int row = row0 + t * 16 + lrr;
        int i = s_idx[t * 16 + lrr];
        if (lj < 6) {
            return points[((size_t)bidx * NN + i) * 6 + lj];
        } else {
            int q = row >> 5, cc = lj - 6;
            return xyz[((size_t)bidx * NN + i) * 3 + cc] - newxyz[(size_t)q * 3 + cc];
        }
    };

    float fcur = 0.f;
    if (ld) fcur = load_feat(0);

    for (int t = 0; t < 8; t++) {
        if (ld) s_f2[t & 1][lrr][lj] = pack2(fcur, fcur);
        __syncthreads();
        if (ld && t < 7) fcur = load_feat(t + 1);

        ull a01 = bp.x, a23 = bp.y;
#pragma unroll
        for (int j = 0; j < 9; j++) {
            ull f = s_f2[t & 1][r][j];
            ulonglong2 w = *reinterpret_cast<const ulonglong2*>(&s_W[j * 64 + c0]);
            a01 = fma2(f, w.x, a01);
            a23 = fma2(f, w.y, a23);
        }
        ulonglong2 o; o.x = a01; o.y = a23;
        *reinterpret_cast<ulonglong2*>(&g_h0[(size_t)(row0 + t * 16 + r) * 64 + c0]) = o;
        ls01 = add2(ls01, a01); ls23 = add2(ls23, a23);
        lq01 = fma2(a01, a01, lq01); lq23 = fma2(a23, a23, lq23);
    }
    float l0, l1, l2, l3;
    unpack2(ls01, l0, l1); unpack2(ls23, l2, l3);
    s_red[r][c0] = l0; s_red[r][c0+1] = l1; s_red[r][c0+2] = l2; s_red[r][c0+3] = l3;
    __syncthreads();
    if (tid < 64) {
        float t0 = 0.f;
#pragma unroll
        for (int rr = 0; rr < 16; rr++) t0 += s_red[rr][tid];
        atomicAdd(&g_sum[tid], (double)t0);
    }
    __syncthreads();
    unpack2(lq01, l0, l1); unpack2(lq23, l2, l3);
    s_red[r][c0] = l0; s_red[r][c0+1] = l1; s_red[r][c0+2] = l2; s_red[r][c0+3] = l3;
    __syncthreads();
    if (tid < 64) {
        float t0 = 0.f;
#pragma unroll
        for (int rr = 0; rr < 16; rr++) t0 += s_red[rr][tid];
        atomicAdd(&g_sq[tid], (double)t0);
    }
}

// -------------------------------- BN finalize --------------------------------
__global__ void k_finalize(const float* __restrict__ g, const float* __restrict__ be,
                           int off, int C) {
    int c = threadIdx.x;
    if (c < C) {
        const double invM = 1.0 / (double)M_ROWS;
        double m = g_sum[off + c] * invM;
        double v = g_sq[off + c] * invM - m * m;
        float rs = rsqrtf((float)v + EPSf);
        float a = g[c] * rs;
        g_a[off + c] = a;
        g_cs[off + c] = fmaf(-(float)m, a, be[c]);
    }
}

// -------------- Layer1: bn0+relu, 64->64 matmul, 2 rows x 8 cols -------------
// xT transposed in smem (plain floats, in-register dup). Warp = 8 cgs x 4 rgs:
// w loads 256B/warp, x loads broadcast. Per-output fma order unchanged.
__global__ void __launch_bounds__(256)
k_layer1(const float* __restrict__ W1, const float* __restrict__ b1) {
    __shared__ __align__(16) float s_W[64 * 64];      // 16 KB
    __shared__ __align__(16) float s_b[64];
    __shared__ float s_a[64], s_cs[64];
    __shared__ __align__(16) float s_xT[64 * 65];     // xT[j][row], padded; aliased as red[32][68]
    int tid = threadIdx.x;
    for (int i = tid; i < 4096; i += 256) s_W[i] = W1[i];
    if (tid < 64) { s_b[tid] = b1[tid]; s_a[tid] = g_a[tid]; s_cs[tid] = g_cs[tid]; }
    __syncthreads();

    int cg = tid & 7, rg = tid >> 3;          // 8 col-groups x 32 row-groups
    int c0 = cg * 8;
    int r0 = rg * 2;
    ulonglong2 bpA = *reinterpret_cast<const ulonglong2*>(&s_b[c0]);
    ulonglong2 bpB = *reinterpret_cast<const ulonglong2*>(&s_b[c0 + 4]);
    ull ls[4] = {0, 0, 0, 0}, lq[4] = {0, 0, 0, 0};

    for (int t = 0; t < 2; t++) {
        int row0 = blockIdx.x * 128 + t * 64;
#pragma unroll
        for (int e = 0; e < 8; e++) {
            int lin = e * 256 + tid;
            int rr = lin >> 5, jj = (lin & 31) * 2;
            float2 v = *reinterpret_cast<const float2*>(&g_h0[(size_t)(row0 + rr) * 64 + jj]);
            s_xT[jj * 65 + rr]       = fmaxf(fmaf(v.x, s_a[jj],     s_cs[jj]),     0.f);
            s_xT[(jj + 1) * 65 + rr] = fmaxf(fmaf(v.y, s_a[jj + 1], s_cs[jj + 1]), 0.f);
        }
        __syncthreads();

        ull a0[4], a1[4];
#pragma unroll
        for (int p = 0; p < 4; p++) {
            a0[p] = (p < 2) ? (p == 0 ? bpA.x : bpA.y) : (p == 2 ? bpB.x : bpB.y);
            a1[p] = a0[p];
        }
#pragma unroll
        for (int j = 0; j < 64; j++) {
            float x0 = s_xT[j * 65 + r0];
            float x1 = s_xT[j * 65 + r0 + 1];
            ull x0d = pack2(x0, x0), x1d = pack2(x1, x1);
            ulonglong2 wA = *reinterpret_cast<const ulonglong2*>(&s_W[j * 64 + c0]);
            ulonglong2 wB = *reinterpret_cast<const ulonglong2*>(&s_W[j * 64 + c0 + 4]);
            a0[0] = fma2(x0d, wA.x, a0[0]); a0[1] = fma2(x0d, wA.y, a0[1]);
            a0[2] = fma2(x0d, wB.x, a0[2]); a0[3] = fma2(x0d, wB.y, a0[3]);
            a1[0] = fma2(x1d, wA.x, a1[0]); a1[1] = fma2(x1d, wA.y, a1[1]);
            a1[2] = fma2(x1d, wB.x, a1[2]); a1[3] = fma2(x1d, wB.y, a1[3]);
        }
        ulonglong2 o;
        o.x = a0[0]; o.y = a0[1];
        *reinterpret_cast<ulonglong2*>(&g_h1[(size_t)(row0 + r0) * 64 + c0]) = o;
        o.x = a0[2]; o.y = a0[3];
        *reinterpret_cast<ulonglong2*>(&g_h1[(size_t)(row0 + r0) * 64 + c0 + 4]) = o;
        o.x = a1[0]; o.y = a1[1];
        *reinterpret_cast<ulonglong2*>(&g_h1[(size_t)(row0 + r0 + 1) * 64 + c0]) = o;
        o.x = a1[2]; o.y = a1[3];
        *reinterpret_cast<ulonglong2*>(&g_h1[(size_t)(row0 + r0 + 1) * 64 + c0 + 4]) = o;
#pragma unroll
        for (int p = 0; p < 4; p++) {
            ls[p] = add2(add2(ls[p], a0[p]), a1[p]);
            lq[p] = fma2(a0[p], a0[p], lq[p]);
            lq[p] = fma2(a1[p], a1[p], lq[p]);
        }
        __syncthreads();
    }

    // stats reduce (alias red[32][68] over s_xT)
    float* red = s_xT;
    {
        float v[8];
#pragma unroll
        for (int p = 0; p < 4; p++) unpack2(ls[p], v[2 * p], v[2 * p + 1]);
#pragma unroll
        for (int i = 0; i < 8; i++) red[rg * 68 + c0 + i] = v[i];
    }
    __syncthreads();
    if (tid < 64) {
        float t0 = 0.f;
#pragma unroll
        for (int rr = 0; rr < 32; rr++) t0 += red[rr * 68 + tid];
        atomicAdd(&g_sum[64 + tid], (double)t0);
    }
    __syncthreads();
    {
        float v[8];
#pragma unroll
        for (int p = 0; p < 4; p++) unpack2(lq[p], v[2 * p], v[2 * p + 1]);
#pragma unroll
        for (int i = 0; i < 8; i++) red[rg * 68 + c0 + i] = v[i];
    }
    __syncthreads();
    if (tid < 64) {
        float t0 = 0.f;
#pragma unroll
        for (int rr = 0; rr < 32; rr++) t0 += red[rr * 68 + tid];
        atomicAdd(&g_sq[64 + tid], (double)t0);
    }
}

// ----- Layer2: bn1+relu, 64->128, 2 rows x 8 cols, fused per-query max/min ----
// Tile = 32 rows = ONE query. Warp = 2 cgs x 16 rgs: w loads are broadcasts.
// h2 never materialized. red buffers alias xT (barriered).
__global__ void __launch_bounds__(256)
k_layer2(const float* __restrict__ W2, const float* __restrict__ b2) {
    __shared__ __align__(16) float s_W[64 * 128];     // 32 KB
    __shared__ __align__(16) float s_b[128];
    __shared__ float s_a[64], s_cs[64];
    __shared__ __align__(16) float s_xT[64 * 33];     // xT[j][row]; aliased as red[16][132]
    int tid = threadIdx.x;
    for (int i = tid; i < 8192; i += 256) s_W[i] = W2[i];
    if (tid < 128) s_b[tid] = b2[tid];
    if (tid < 64) { s_a[tid] = g_a[64 + tid]; s_cs[tid] = g_cs[64 + tid]; }
    __syncthreads();

    int rg = tid & 15, cg = tid >> 4;        // 16 rgs x 16 cgs
    int c0 = cg * 8;
    int r0 = rg * 2;
    ulonglong2 bpA = *reinterpret_cast<const ulonglong2*>(&s_b[c0]);
    ulonglong2 bpB = *reinterpret_cast<const ulonglong2*>(&s_b[c0 + 4]);
    ull ls[4] = {0, 0, 0, 0}, lq[4] = {0, 0, 0, 0};
    float* red = s_xT;

    for (int t = 0; t < 4; t++) {
        int row0 = blockIdx.x * 128 + t * 32;
        int q = blockIdx.x * 4 + t;
#pragma unroll
        for (int e = 0; e < 4; e++) {
            int lin = e * 256 + tid;
            int rr = lin >> 5, jj = (lin & 31) * 2;
            float2 v = *reinterpret_cast<const float2*>(&g_h1[(size_t)(row0 + rr) * 64 + jj]);
            s_xT[jj * 33 + rr]       = fmaxf(fmaf(v.x, s_a[jj],     s_cs[jj]),     0.f);
            s_xT[(jj + 1) * 33 + rr] = fmaxf(fmaf(v.y, s_a[jj + 1], s_cs[jj + 1]), 0.f);
        }
        __syncthreads();

        ull a0[4], a1[4];
        a0[0] = bpA.x; a0[1] = bpA.y; a0[2] = bpB.x; a0[3] = bpB.y;
        a1[0] = bpA.x; a1[1] = bpA.y; a1[2] = bpB.x; a1[3] = bpB.y;
#pragma unroll
        for (int j = 0; j < 64; j++) {
            float x0 = s_xT[j * 33 + r0];
            float x1 = s_xT[j * 33 + r0 + 1];
            ull x0d = pack2(x0, x0), x1d = pack2(x1, x1);
            ulonglong2 wA = *reinterpret_cast<const ulonglong2*>(&s_W[j * 128 + c0]);
            ulonglong2 wB = *reinterpret_cast<const ulonglong2*>(&s_W[j * 128 + c0 + 4]);
            a0[0] = fma2(x0d, wA.x, a0[0]); a0[1] = fma2(x0d, wA.y, a0[1]);
            a0[2] = fma2(x0d, wB.x, a0[2]); a0[3] = fma2(x0d, wB.y, a0[3]);
            a1[0] = fma2(x1d, wA.x, a1[0]); a1[1] = fma2(x1d, wA.y, a1[1]);
            a1[2] = fma2(x1d, wB.x, a1[2]); a1[3] = fma2(x1d, wB.y, a1[3]);
        }
#pragma unroll
        for (int p = 0; p < 4; p++) {
            ls[p] = add2(add2(ls[p], a0[p]), a1[p]);
            lq[p] = fma2(a0[p], a0[p], lq[p]);
            lq[p] = fma2(a1[p], a1[p], lq[p]);
        }
        float e0[8], e1[8];
#pragma unroll
        for (int p = 0; p < 4; p++) {
            unpack2(a0[p], e0[2 * p], e0[2 * p + 1]);
            unpack2(a1[p], e1[2 * p], e1[2 * p + 1]);
        }
        __syncthreads();                      // done reading xT
#pragma unroll
        for (int i = 0; i < 8; i++) red[rg * 132 + c0 + i] = fmaxf(e0[i], e1[i]);
        __syncthreads();
        if (tid < 128) {
            float m = red[tid];
#pragma unroll
            for (int rr = 1; rr < 16; rr++) m = fmaxf(m, red[rr * 132 + tid]);
            g_mx[(size_t)q * 128 + tid] = m;
        }
        __syncthreads();
#pragma unroll
        for (int i = 0; i < 8; i++) red[rg * 132 + c0 + i] = fminf(e0[i], e1[i]);
        __syncthreads();
        if (tid < 128) {
            float m = red[tid];
#pragma unroll
            for (int rr = 1; rr < 16; rr++) m = fminf(m, red[rr * 132 + tid]);
            g_mn[(size_t)q * 128 + tid] = m;
        }
        __syncthreads();                      // before next tile's xT writes
    }

    // stats (alias red over xT)
    {
        float v[8];
#pragma unroll
        for (int p = 0; p < 4; p++) unpack2(ls[p], v[2 * p], v[2 * p + 1]);
#pragma unroll
        for (int i = 0; i < 8; i++) red[rg * 132 + c0 + i] = v[i];
    }
    __syncthreads();
    if (tid < 128) {
        float t0 = 0.f;
#pragma unroll
        for (int rr = 0; rr < 16; rr++) t0 += red[rr * 132 + tid];
        atomicAdd(&g_sum[128 + tid], (double)t0);
    }
    __syncthreads();
    {
        float v[8];
#pragma unroll
        for (int p = 0; p < 4; p++) unpack2(lq[p], v[2 * p], v[2 * p + 1]);
#pragma unroll
        for (int i = 0; i < 8; i++) red[rg * 132 + c0 + i] = v[i];
    }
    __syncthreads();
    if (tid < 128) {
        float t0 = 0.f;
#pragma unroll
        for (int rr = 0; rr < 16; rr++) t0 += red[rr * 132 + tid];
        atomicAdd(&g_sq[128 + tid], (double)t0);
    }
}

// --------- Final: BN2+relu applied to per-query max/min (exact fusion) -------
__global__ void __launch_bounds__(256)
k_out(float* __restrict__ out) {
    int i = blockIdx.x * 256 + threadIdx.x;
    int c = i & 127;
    float a = g_a[128 + c], cs = g_cs[128 + c];
    float v = (a >= 0.f) ? g_mx[i] : g_mn[i];
    out[(size_t)BB * SS * 3 + i] = fmaxf(fmaf(v, a, cs), 0.f);
}

// -----------------------------------------------------------------------------
extern "C" void kernel_launch(void* const* d_in, const int* in_sizes, int n_in,
                              void* d_out, int out_size) {
    const float* xyz    = (const float*)d_in[0];
    const float* points = (const float*)d_in[1];
    const float* W0 = (const float*)d_in[2];  const float* b0 = (const float*)d_in[3];
    const float* g0 = (const float*)d_in[4];  const float* be0 = (const float*)d_in[5];
    const float* W1 = (const float*)d_in[6];  const float* b1 = (const float*)d_in[7];
    const float* g1 = (const float*)d_in[8];  const float* be1 = (const float*)d_in[9];
    const float* W2 = (const float*)d_in[10]; const float* b2 = (const float*)d_in[11];
    const float* g2 = (const float*)d_in[12]; const float* be2 = (const float*)d_in[13];
    float* out = (float*)d_out;   // [B*S*3 new_xyz | B*S*128 new_points]

    k_init<<<1, 256>>>();
    k_fps<<<BB, 512>>>(xyz, out);
    k_ball<<<(BB * SS) / 8, 256>>>(xyz, out);
    k_layer0<<<2048, 256>>>(points, xyz, out, W0, b0);
    k_finalize<<<1, 64>>>(g0, be0, 0, 64);
    k_layer1<<<2048, 256>>>(W1, b1);
    k_finalize<<<1, 64>>>(g1, be1, 64, 64);
    k_layer2<<<2048, 256>>>(W2, b2);
    k_finalize<<<1, 128>>>(g2, be2, 128, 128);
    k_out<<<(BB * SS * 128) / 256, 256>>>(out);
}